// round 14
// baseline (speedup 1.0000x reference)
#include <cuda_runtime.h>
#include <cuda_fp16.h>
#include <cstdint>

typedef unsigned long long ull;
typedef unsigned int u32;

// ---------------- global scratch (static, no allocs) ----------------
// Bh fragment image for direct LDG.128:
//   uint4 index: (((ks*2+h)*4+cg)*4+np)*32 + lane   (lane = q*4+jj)
__device__ __align__(16) u32 g_EimgH[32768];     // 128KB
__device__ float g_hhalf[512];     // 0.5*||e_c||^2 (fp32)
__device__ int g_emax2bits;        // max ||e_c||^2 as float bits (zero-init)

#define KEPS 1.25e-3f
#define CMAX 16
#define ZRS 144                    // Z plane row stride (u32); 32 rows per plane

__device__ __forceinline__ u32 packsplit_hi(float v0, float v1, float& r0, float& r1) {
    __half h0 = __float2half_rn(v0), h1 = __float2half_rn(v1);
    r0 = v0 - __half2float(h0);
    r1 = v1 - __half2float(h1);
    return (u32)__half_as_ushort(h0) | ((u32)__half_as_ushort(h1) << 16);
}
__device__ __forceinline__ u32 pack_lo(float r0, float r1) {
    __half l0 = __float2half_rn(r0), l1 = __float2half_rn(r1);
    return (u32)__half_as_ushort(l0) | ((u32)__half_as_ushort(l1) << 16);
}
__device__ __forceinline__ unsigned fkey(float f) {   // monotonic float->uint
    unsigned u = __float_as_uint(f);
    return (u & 0x80000000u) ? ~u : (u | 0x80000000u);
}
__device__ __forceinline__ float unfkey(u32 k) {
    u32 u = (k & 0x80000000u) ? (k & 0x7fffffffu) : ~k;
    return __uint_as_float(u);
}
__device__ __forceinline__ void mma16(float* c, u32 a0, u32 a1, u32 a2, u32 a3,
                                      u32 b0, u32 b1) {
    asm("mma.sync.aligned.m16n8k16.row.col.f32.f16.f16.f32 "
        "{%0,%1,%2,%3}, {%4,%5,%6,%7}, {%8,%9}, {%0,%1,%2,%3};"
        : "+f"(c[0]), "+f"(c[1]), "+f"(c[2]), "+f"(c[3])
        : "r"(a0), "r"(a1), "r"(a2), "r"(a3), "r"(b0), "r"(b1));
}

// ---------------- prep: n-paired Bh fragment image + norms ----------------
__global__ void vq_prep(const float* __restrict__ emb) {
    int t = blockIdx.x * blockDim.x + threadIdx.x;
    int nt = gridDim.x * blockDim.x;
    for (int i = t; i < 512 * 64; i += nt) {       // (code, kpair)
        int code = i >> 6, p = i & 63;
        float v0 = emb[code * 128 + 2 * p], v1 = emb[code * 128 + 2 * p + 1];
        float r0, r1;
        u32 hi = packsplit_hi(v0, v1, r0, r1);
        int ks = p >> 3, pp = p & 7, jj = pp & 3, s = pp >> 2;
        int h = code >> 8, c8 = code & 255;
        int cg = c8 >> 6, rem = c8 & 63, n = rem >> 3, q = rem & 7;
        int np = n >> 1, no = n & 1;
        int idx = ((((ks * 2 + h) * 4 + cg) * 4 + np) * 32 + q * 4 + jj) * 4 + no * 2 + s;
        g_EimgH[idx] = hi;
    }
    if (t < 512) {
        const float* row = emb + t * 128;
        float s2 = 0.f;
        #pragma unroll 4
        for (int c = 0; c < 128; ++c) { float v = row[c]; s2 += v * v; }
        g_hhalf[t] = 0.5f * s2;
        atomicMax(&g_emax2bits, __float_as_int(s2));
    }
}

// ---------------- main kernel ----------------
// Z plane layout (pair-interleaved, mma-ordered quads) — see round 12.
#define ZHOFF  0          // 32 x 144
#define ZLOFF  4608       // 32 x 144
#define HHOFF  9216       // 512 floats
#define ZNOFF  9728       // 64 floats
#define BSTOFF 9792       // 64 u32 (fkey bits)
#define CDOFF  9856       // 64 x 16 floats
#define CCOFF  10880      // 64 x 16 u32
#define CNTOFF 11904      // 64 u32
#define FIOFF  11968      // 64 u32
#define SMEM_BYTES (12032 * 4)
#define QS_STRIDE 68

__device__ __forceinline__ u32 zpos(int px, int p) {   // u32 index within a plane
    int r = (px >> 4) * 8 + (px & 7), s = (px >> 3) & 1;
    int ks = p >> 3, c = p & 7;
    return (u32)(r * ZRS + (ks * 4 + (((c & 3) + (r >> 1)) & 3)) * 4 + (c >> 2) * 2 + s);
}

__device__ __forceinline__ float rescore_dot(const u32* __restrict__ ZH,
                                             const u32* __restrict__ ZL,
                                             const float* __restrict__ emb,
                                             int px, int cc, int lane) {
    int p0 = 2 * lane, p1 = p0 + 1;
    u32 o0 = zpos(px, p0), o1 = zpos(px, p1);
    float2 a0 = __half22float2(*(const __half2*)&ZH[o0]);
    float2 b0 = __half22float2(*(const __half2*)&ZL[o0]);
    float2 a1 = __half22float2(*(const __half2*)&ZH[o1]);
    float2 b1 = __half22float2(*(const __half2*)&ZL[o1]);
    float4 e = *(const float4*)(emb + (size_t)cc * 128 + 4 * lane);
    float part = (a0.x + b0.x) * e.x + (a0.y + b0.y) * e.y
               + (a1.x + b1.x) * e.z + (a1.y + b1.y) * e.w;
    #pragma unroll
    for (int d = 16; d; d >>= 1) part += __shfl_xor_sync(0xffffffffu, part, d);
    return part;
}

__global__ __launch_bounds__(256, 2)
void vq_mma_kernel(const float* __restrict__ z, const float* __restrict__ emb,
                   float* __restrict__ out) {
    extern __shared__ float SMF[];
    u32* ZU = (u32*)SMF;
    const u32* ZH = ZU + ZHOFF;
    const u32* ZL = ZU + ZLOFF;
    float* hh_s = SMF + HHOFF;
    float* znorm = SMF + ZNOFF;
    u32* bestB = ZU + BSTOFF;
    float* candD = SMF + CDOFF;
    u32* candC = ZU + CCOFF;
    u32* cnt_s = ZU + CNTOFF;
    u32* fidx = ZU + FIOFF;

    const int tid = threadIdx.x;
    const int wid = tid >> 5, lane = tid & 31;
    const int jj = lane & 3, q = lane >> 2;
    const int pg = wid & 1, cg = wid >> 1;          // 2 px-groups x 4 code-groups
    const int px0 = pg << 5;
    const int b = blockIdx.x >> 6;
    const int p0 = (blockIdx.x & 63) << 6;          // 64-px tile

    const float* zb = z + (size_t)b * 128 * 4096 + p0;

    hh_s[tid] = g_hhalf[tid];
    hh_s[tid + 256] = g_hhalf[tid + 256];
    if (tid < 64) { bestB[tid] = 0xFFFFFFFFu; znorm[tid] = 0.f; cnt_s[tid] = 0u; }
    __syncthreads();

    // ---- Z producer: thread = (row r, k-group kg); wide STS.128 writes ----
    {
        int r = tid & 31, kg = tid >> 5;
        int px_a = (r >> 3) * 16 + (r & 7);         // s = 0
        int px_b = px_a + 8;                        // s = 1
        u32 hiA[8], loA[8], hiB[8], loB[8];
        float sa = 0.f, sb = 0.f;
        #pragma unroll
        for (int c = 0; c < 8; ++c) {               // kpair p = kg*8+c
            const float* zc = zb + (size_t)(kg * 8 + c) * 2 * 4096;
            float va0 = zc[px_a], va1 = zc[4096 + px_a];
            float vb0 = zc[px_b], vb1 = zc[4096 + px_b];
            float r0, r1;
            hiA[c] = packsplit_hi(va0, va1, r0, r1);
            loA[c] = pack_lo(r0, r1);
            sa += va0 * va0 + va1 * va1;
            hiB[c] = packsplit_hi(vb0, vb1, r0, r1);
            loB[c] = pack_lo(r0, r1);
            sb += vb0 * vb0 + vb1 * vb1;
        }
        u32* Zh = ZU + ZHOFF + r * ZRS;
        u32* Zl = ZU + ZLOFF + r * ZRS;
        int rs = r >> 1;
        #pragma unroll
        for (int j = 0; j < 4; ++j) {               // quad j: kpairs {j, j+4}
            int pq = (kg * 4 + ((j + rs) & 3)) * 4;
            *(uint4*)(Zh + pq) = make_uint4(hiA[j], hiB[j], hiA[j + 4], hiB[j + 4]);
            *(uint4*)(Zl + pq) = make_uint4(loA[j], loB[j], loA[j + 4], loB[j + 4]);
        }
        atomicAdd(&znorm[px_a], sa);
        atomicAdd(&znorm[px_b], sb);
    }
    __syncthreads();

    const float emax2 = __int_as_float(g_emax2bits);
    const u32* Arow0 = ZH + ((pg * 2 + 0) * 8 + q) * ZRS;   // m=0: px0+q / px0+q+8
    const u32* Arow1 = ZH + ((pg * 2 + 1) * 8 + q) * ZRS;   // m=1: px0+16+q / +24
    const int qsw = (q >> 1) & 3;

    for (int h = 0; h < 2; ++h) {
        float acc[2][8][4];
        #pragma unroll
        for (int m = 0; m < 2; ++m)
            #pragma unroll
            for (int n = 0; n < 8; ++n)
                #pragma unroll
                for (int r = 0; r < 4; ++r) acc[m][n][r] = 0.f;

        #pragma unroll
        for (int ks = 0; ks < 8; ++ks) {
            int pq = (ks * 4 + ((jj + qsw) & 3)) * 4;
            uint4 A0 = *(const uint4*)(Arow0 + pq);   // [a0 a1 a2 a3] mma order
            uint4 A1 = *(const uint4*)(Arow1 + pq);
            const uint4* e4 = (const uint4*)g_EimgH
                              + (size_t)(((ks * 2 + h) * 4 + cg) * 4) * 32 + lane;
            #pragma unroll
            for (int np = 0; np < 4; ++np) {
                uint4 B = __ldg(e4 + np * 32);
                mma16(acc[0][2 * np],     A0.x, A0.y, A0.z, A0.w, B.x, B.y);
                mma16(acc[1][2 * np],     A1.x, A1.y, A1.z, A1.w, B.x, B.y);
                mma16(acc[0][2 * np + 1], A0.x, A0.y, A0.z, A0.w, B.z, B.w);
                mma16(acc[1][2 * np + 1], A1.x, A1.y, A1.z, A1.w, B.z, B.w);
            }
        }

        // ---- phase-1 epilogue: hoisted hh + float-only min + candidates ----
        float2 hhv[8];
        #pragma unroll
        for (int n = 0; n < 8; ++n)
            hhv[n] = *(const float2*)&hh_s[h * 256 + cg * 64 + 8 * n + 2 * jj];

        #pragma unroll
        for (int m = 0; m < 2; ++m) {
            int rowA = px0 + 16 * m + q, rowB = rowA + 8;
            float mnA = 1e30f, mnB = 1e30f;
            #pragma unroll
            for (int n = 0; n < 8; ++n) {
                mnA = fminf(mnA, fminf(hhv[n].x - acc[m][n][0], hhv[n].y - acc[m][n][1]));
                mnB = fminf(mnB, fminf(hhv[n].x - acc[m][n][2], hhv[n].y - acc[m][n][3]));
            }
            #pragma unroll
            for (int d = 1; d <= 2; d <<= 1) {
                mnA = fminf(mnA, __shfl_xor_sync(0xffffffffu, mnA, d));
                mnB = fminf(mnB, __shfl_xor_sync(0xffffffffu, mnB, d));
            }
            u32 kA = fkey(mnA), kB = fkey(mnB);
            u32 curA = *(volatile u32*)&bestB[rowA];
            u32 curB = *(volatile u32*)&bestB[rowB];
            float MA = KEPS * sqrtf(znorm[rowA] * emax2);
            float MB = KEPS * sqrtf(znorm[rowB] * emax2);
            float thA = unfkey(kA < curA ? kA : curA) + 2.f * MA;
            float thB = unfkey(kB < curB ? kB : curB) + 2.f * MB;
            if (jj == 0) {
                atomicMin(&bestB[rowA], kA);
                atomicMin(&bestB[rowB], kB);
            }
            #pragma unroll
            for (int n = 0; n < 8; ++n) {
                int c = h * 256 + cg * 64 + 8 * n + 2 * jj;
                float d0A = hhv[n].x - acc[m][n][0], d1A = hhv[n].y - acc[m][n][1];
                float d0B = hhv[n].x - acc[m][n][2], d1B = hhv[n].y - acc[m][n][3];
                if (d0A <= thA) { u32 s = atomicAdd(&cnt_s[rowA], 1u); if (s < CMAX) { candD[rowA * CMAX + s] = d0A; candC[rowA * CMAX + s] = (u32)c; } }
                if (d1A <= thA) { u32 s = atomicAdd(&cnt_s[rowA], 1u); if (s < CMAX) { candD[rowA * CMAX + s] = d1A; candC[rowA * CMAX + s] = (u32)(c + 1); } }
                if (d0B <= thB) { u32 s = atomicAdd(&cnt_s[rowB], 1u); if (s < CMAX) { candD[rowB * CMAX + s] = d0B; candC[rowB * CMAX + s] = (u32)c; } }
                if (d1B <= thB) { u32 s = atomicAdd(&cnt_s[rowB], 1u); if (s < CMAX) { candD[rowB * CMAX + s] = d1B; candC[rowB * CMAX + s] = (u32)(c + 1); } }
            }
        }
    }

    __syncthreads();   // phase-1 complete: bestB/cand/cnt final

    // ---- phase-2: candidate set provably contains the exact winner.
    //      cnt==1  -> that candidate IS the winner (no rescore needed).
    //      2..CMAX -> exact fp32 rescore of the candidates.
    //      >CMAX   -> full 512-code fp32 rescan (overflow fallback).
    for (int i = 0; i < 8; ++i) {
        int px = wid * 8 + i;
        u32 c = cnt_s[px];
        if (c == 1) {
            if (lane == 0) fidx[px] = candC[px * CMAX];
            continue;
        }
        float M = KEPS * sqrtf(znorm[px] * emax2);
        float th = unfkey(bestB[px]) + 2.f * M;
        ull best = ~0ull;
        if (c <= CMAX) {
            for (u32 j = 0; j < c; ++j) {
                if (candD[px * CMAX + j] <= th) {
                    u32 cc = candC[px * CMAX + j];
                    float d = hh_s[cc] - rescore_dot(ZH, ZL, emb, px, (int)cc, lane);
                    ull key = ((ull)fkey(d) << 32) | cc;
                    if (key < best) best = key;
                }
            }
        } else {
            for (int cc = 0; cc < 512; ++cc) {
                float d = hh_s[cc] - rescore_dot(ZH, ZL, emb, px, cc, lane);
                ull key = ((ull)fkey(d) << 32) | (u32)cc;
                if (key < best) best = key;
            }
        }
        if (lane == 0) fidx[px] = (u32)best;
    }

    __syncthreads();   // fidx final; Z planes reusable as gather staging

    // ---- gather winning rows into Qs[c][px], then coalesced write ----
    {
        int px = tid >> 2, qu = tid & 3;
        u32 idx = fidx[px];
        const float* er = emb + (size_t)idx * 128 + 32 * qu;
        float* Qs = SMF;
        #pragma unroll
        for (int i = 0; i < 8; ++i) {
            float4 v = *(const float4*)(er + 4 * i);
            int c = 32 * qu + 4 * i;
            Qs[(c + 0) * QS_STRIDE + px] = v.x;
            Qs[(c + 1) * QS_STRIDE + px] = v.y;
            Qs[(c + 2) * QS_STRIDE + px] = v.z;
            Qs[(c + 3) * QS_STRIDE + px] = v.w;
        }
    }
    __syncthreads();
    {
        int r = tid >> 1, half = tid & 1;           // 128 ch x 2 halves of 32px
        float* orow = out + (size_t)b * 128 * 4096 + (size_t)r * 4096 + p0 + 32 * half;
        const float* qrow = SMF + r * QS_STRIDE + 32 * half;
        #pragma unroll
        for (int i = 0; i < 8; ++i)
            *(float4*)(orow + 4 * i) = *(const float4*)(qrow + 4 * i);
    }
}

extern "C" void kernel_launch(void* const* d_in, const int* in_sizes, int n_in,
                              void* d_out, int out_size) {
    const float* z   = (const float*)d_in[0];   // (32,128,64,64) fp32
    const float* emb = (const float*)d_in[1];   // (512,128) fp32
    float* out = (float*)d_out;

    cudaFuncSetAttribute(vq_mma_kernel,
                         cudaFuncAttributeMaxDynamicSharedMemorySize, SMEM_BYTES);

    vq_prep<<<64, 256>>>(emb);
    vq_mma_kernel<<<2048, 256, SMEM_BYTES>>>(z, emb, out);
}

// round 15
// speedup vs baseline: 1.5486x; 1.5486x over previous
#include <cuda_runtime.h>
#include <cuda_fp16.h>
#include <cstdint>

typedef unsigned long long ull;
typedef unsigned int u32;

// ---------------- global scratch (static, no allocs) ----------------
// Bh fragment image for direct LDG.128:
//   uint4 index: (((ks*2+h)*4+cg)*4+np)*32 + lane   (lane = q*4+jj)
__device__ __align__(16) u32 g_EimgH[32768];     // 128KB
__device__ float g_hhalf[512];     // 0.5*||e_c||^2 (fp32)
__device__ int g_emax2bits;        // max ||e_c||^2 as float bits (zero-init)

#define KEPS 1.25e-3f
#define CMAX 16
#define ZRS 144                    // Z plane row stride (u32); 32 rows per plane

__device__ __forceinline__ u32 packsplit_hi(float v0, float v1, float& r0, float& r1) {
    __half h0 = __float2half_rn(v0), h1 = __float2half_rn(v1);
    r0 = v0 - __half2float(h0);
    r1 = v1 - __half2float(h1);
    return (u32)__half_as_ushort(h0) | ((u32)__half_as_ushort(h1) << 16);
}
__device__ __forceinline__ u32 pack_lo(float r0, float r1) {
    __half l0 = __float2half_rn(r0), l1 = __float2half_rn(r1);
    return (u32)__half_as_ushort(l0) | ((u32)__half_as_ushort(l1) << 16);
}
__device__ __forceinline__ unsigned fkey(float f) {   // monotonic float->uint
    unsigned u = __float_as_uint(f);
    return (u & 0x80000000u) ? ~u : (u | 0x80000000u);
}
__device__ __forceinline__ float unfkey(u32 k) {
    u32 u = (k & 0x80000000u) ? (k & 0x7fffffffu) : ~k;
    return __uint_as_float(u);
}
__device__ __forceinline__ void mma16(float* c, u32 a0, u32 a1, u32 a2, u32 a3,
                                      u32 b0, u32 b1) {
    asm("mma.sync.aligned.m16n8k16.row.col.f32.f16.f16.f32 "
        "{%0,%1,%2,%3}, {%4,%5,%6,%7}, {%8,%9}, {%0,%1,%2,%3};"
        : "+f"(c[0]), "+f"(c[1]), "+f"(c[2]), "+f"(c[3])
        : "r"(a0), "r"(a1), "r"(a2), "r"(a3), "r"(b0), "r"(b1));
}

// ---------------- prep: n-paired Bh fragment image + norms ----------------
__global__ void vq_prep(const float* __restrict__ emb) {
    int t = blockIdx.x * blockDim.x + threadIdx.x;
    int nt = gridDim.x * blockDim.x;
    for (int i = t; i < 512 * 64; i += nt) {       // (code, kpair)
        int code = i >> 6, p = i & 63;
        float v0 = emb[code * 128 + 2 * p], v1 = emb[code * 128 + 2 * p + 1];
        float r0, r1;
        u32 hi = packsplit_hi(v0, v1, r0, r1);
        int ks = p >> 3, pp = p & 7, jj = pp & 3, s = pp >> 2;
        int h = code >> 8, c8 = code & 255;
        int cg = c8 >> 6, rem = c8 & 63, n = rem >> 3, q = rem & 7;
        int np = n >> 1, no = n & 1;
        int idx = ((((ks * 2 + h) * 4 + cg) * 4 + np) * 32 + q * 4 + jj) * 4 + no * 2 + s;
        g_EimgH[idx] = hi;
    }
    if (t < 512) {
        const float* row = emb + t * 128;
        float s2 = 0.f;
        #pragma unroll 4
        for (int c = 0; c < 128; ++c) { float v = row[c]; s2 += v * v; }
        g_hhalf[t] = 0.5f * s2;
        atomicMax(&g_emax2bits, __float_as_int(s2));
    }
}

// ---------------- main kernel ----------------
// Z plane layout (pair-interleaved, mma-ordered quads) — see round 12.
#define ZHOFF  0          // 32 x 144
#define ZLOFF  4608       // 32 x 144
#define HHOFF  9216       // 512 floats
#define ZNOFF  9728       // 64 floats
#define BSTOFF 9792       // 64 u32 (fkey bits)
#define CDOFF  9856       // 64 x 16 floats
#define CCOFF  10880      // 64 x 16 u32
#define CNTOFF 11904      // 64 u32
#define FIOFF  11968      // 64 u32
#define SMEM_BYTES (12032 * 4)
#define QS_STRIDE 68

__device__ __forceinline__ u32 zpos(int px, int p) {   // u32 index within a plane
    int r = (px >> 4) * 8 + (px & 7), s = (px >> 3) & 1;
    int ks = p >> 3, c = p & 7;
    return (u32)(r * ZRS + (ks * 4 + (((c & 3) + (r >> 1)) & 3)) * 4 + (c >> 2) * 2 + s);
}

__device__ __forceinline__ float rescore_dot(const u32* __restrict__ ZH,
                                             const u32* __restrict__ ZL,
                                             const float* __restrict__ emb,
                                             int px, int cc, int lane) {
    int p0 = 2 * lane, p1 = p0 + 1;
    u32 o0 = zpos(px, p0), o1 = zpos(px, p1);
    float2 a0 = __half22float2(*(const __half2*)&ZH[o0]);
    float2 b0 = __half22float2(*(const __half2*)&ZL[o0]);
    float2 a1 = __half22float2(*(const __half2*)&ZH[o1]);
    float2 b1 = __half22float2(*(const __half2*)&ZL[o1]);
    float4 e = *(const float4*)(emb + (size_t)cc * 128 + 4 * lane);
    float part = (a0.x + b0.x) * e.x + (a0.y + b0.y) * e.y
               + (a1.x + b1.x) * e.z + (a1.y + b1.y) * e.w;
    #pragma unroll
    for (int d = 16; d; d >>= 1) part += __shfl_xor_sync(0xffffffffu, part, d);
    return part;
}

__global__ __launch_bounds__(256, 2)
void vq_mma_kernel(const float* __restrict__ z, const float* __restrict__ emb,
                   float* __restrict__ out) {
    extern __shared__ float SMF[];
    u32* ZU = (u32*)SMF;
    const u32* ZH = ZU + ZHOFF;
    const u32* ZL = ZU + ZLOFF;
    float* hh_s = SMF + HHOFF;
    float* znorm = SMF + ZNOFF;
    u32* bestB = ZU + BSTOFF;
    float* candD = SMF + CDOFF;
    u32* candC = ZU + CCOFF;
    u32* cnt_s = ZU + CNTOFF;
    u32* fidx = ZU + FIOFF;

    const int tid = threadIdx.x;
    const int wid = tid >> 5, lane = tid & 31;
    const int jj = lane & 3, q = lane >> 2;
    const int pg = wid & 1, cg = wid >> 1;          // 2 px-groups x 4 code-groups
    const int px0 = pg << 5;
    const int b = blockIdx.x >> 6;
    const int p0 = (blockIdx.x & 63) << 6;          // 64-px tile

    const float* zb = z + (size_t)b * 128 * 4096 + p0;

    hh_s[tid] = g_hhalf[tid];
    hh_s[tid + 256] = g_hhalf[tid + 256];
    if (tid < 64) { bestB[tid] = 0xFFFFFFFFu; znorm[tid] = 0.f; cnt_s[tid] = 0u; }
    __syncthreads();

    // ---- Z producer: thread = (row r, k-group kg); wide STS.128 writes ----
    {
        int r = tid & 31, kg = tid >> 5;
        int px_a = (r >> 3) * 16 + (r & 7);         // s = 0
        int px_b = px_a + 8;                        // s = 1
        u32 hiA[8], loA[8], hiB[8], loB[8];
        float sa = 0.f, sb = 0.f;
        #pragma unroll
        for (int c = 0; c < 8; ++c) {               // kpair p = kg*8+c
            const float* zc = zb + (size_t)(kg * 8 + c) * 2 * 4096;
            float va0 = zc[px_a], va1 = zc[4096 + px_a];
            float vb0 = zc[px_b], vb1 = zc[4096 + px_b];
            float r0, r1;
            hiA[c] = packsplit_hi(va0, va1, r0, r1);
            loA[c] = pack_lo(r0, r1);
            sa += va0 * va0 + va1 * va1;
            hiB[c] = packsplit_hi(vb0, vb1, r0, r1);
            loB[c] = pack_lo(r0, r1);
            sb += vb0 * vb0 + vb1 * vb1;
        }
        u32* Zh = ZU + ZHOFF + r * ZRS;
        u32* Zl = ZU + ZLOFF + r * ZRS;
        int rs = r >> 1;
        #pragma unroll
        for (int j = 0; j < 4; ++j) {               // quad j: kpairs {j, j+4}
            int pq = (kg * 4 + ((j + rs) & 3)) * 4;
            *(uint4*)(Zh + pq) = make_uint4(hiA[j], hiB[j], hiA[j + 4], hiB[j + 4]);
            *(uint4*)(Zl + pq) = make_uint4(loA[j], loB[j], loA[j + 4], loB[j + 4]);
        }
        atomicAdd(&znorm[px_a], sa);
        atomicAdd(&znorm[px_b], sb);
    }
    __syncthreads();

    const float emax2 = __int_as_float(g_emax2bits);
    const u32* Arow0 = ZH + ((pg * 2 + 0) * 8 + q) * ZRS;   // m=0: px0+q / px0+q+8
    const u32* Arow1 = ZH + ((pg * 2 + 1) * 8 + q) * ZRS;   // m=1: px0+16+q / +24
    const int qsw = (q >> 1) & 3;

    for (int h = 0; h < 2; ++h) {
        float acc[2][8][4];
        #pragma unroll
        for (int m = 0; m < 2; ++m)
            #pragma unroll
            for (int n = 0; n < 8; ++n)
                #pragma unroll
                for (int r = 0; r < 4; ++r) acc[m][n][r] = 0.f;

        #pragma unroll
        for (int ks = 0; ks < 8; ++ks) {
            int pq = (ks * 4 + ((jj + qsw) & 3)) * 4;
            uint4 A0 = *(const uint4*)(Arow0 + pq);   // [a0 a1 a2 a3] mma order
            uint4 A1 = *(const uint4*)(Arow1 + pq);
            const uint4* e4 = (const uint4*)g_EimgH
                              + (size_t)(((ks * 2 + h) * 4 + cg) * 4) * 32 + lane;
            #pragma unroll
            for (int np = 0; np < 4; ++np) {
                uint4 B = __ldg(e4 + np * 32);
                mma16(acc[0][2 * np],     A0.x, A0.y, A0.z, A0.w, B.x, B.y);
                mma16(acc[1][2 * np],     A1.x, A1.y, A1.z, A1.w, B.x, B.y);
                mma16(acc[0][2 * np + 1], A0.x, A0.y, A0.z, A0.w, B.z, B.w);
                mma16(acc[1][2 * np + 1], A1.x, A1.y, A1.z, A1.w, B.z, B.w);
            }
        }

        // ---- phase-1 epilogue: float-only min + candidate collection ----
        #pragma unroll
        for (int m = 0; m < 2; ++m) {
            int rowA = px0 + 16 * m + q, rowB = rowA + 8;
            float mnA = 1e30f, mnB = 1e30f;
            #pragma unroll
            for (int n = 0; n < 8; ++n) {
                int c = h * 256 + cg * 64 + 8 * n + 2 * jj;
                float hc0 = hh_s[c], hc1 = hh_s[c + 1];
                mnA = fminf(mnA, fminf(hc0 - acc[m][n][0], hc1 - acc[m][n][1]));
                mnB = fminf(mnB, fminf(hc0 - acc[m][n][2], hc1 - acc[m][n][3]));
            }
            #pragma unroll
            for (int d = 1; d <= 2; d <<= 1) {
                mnA = fminf(mnA, __shfl_xor_sync(0xffffffffu, mnA, d));
                mnB = fminf(mnB, __shfl_xor_sync(0xffffffffu, mnB, d));
            }
            u32 kA = fkey(mnA), kB = fkey(mnB);
            u32 curA = *(volatile u32*)&bestB[rowA];
            u32 curB = *(volatile u32*)&bestB[rowB];
            float MA = KEPS * sqrtf(znorm[rowA] * emax2);
            float MB = KEPS * sqrtf(znorm[rowB] * emax2);
            float thA = unfkey(kA < curA ? kA : curA) + 2.f * MA;
            float thB = unfkey(kB < curB ? kB : curB) + 2.f * MB;
            if (jj == 0) {
                atomicMin(&bestB[rowA], kA);
                atomicMin(&bestB[rowB], kB);
            }
            #pragma unroll
            for (int n = 0; n < 8; ++n) {
                int c = h * 256 + cg * 64 + 8 * n + 2 * jj;
                float hc0 = hh_s[c], hc1 = hh_s[c + 1];
                float d0A = hc0 - acc[m][n][0], d1A = hc1 - acc[m][n][1];
                float d0B = hc0 - acc[m][n][2], d1B = hc1 - acc[m][n][3];
                if (d0A <= thA) { u32 s = atomicAdd(&cnt_s[rowA], 1u); if (s < CMAX) { candD[rowA * CMAX + s] = d0A; candC[rowA * CMAX + s] = (u32)c; } }
                if (d1A <= thA) { u32 s = atomicAdd(&cnt_s[rowA], 1u); if (s < CMAX) { candD[rowA * CMAX + s] = d1A; candC[rowA * CMAX + s] = (u32)(c + 1); } }
                if (d0B <= thB) { u32 s = atomicAdd(&cnt_s[rowB], 1u); if (s < CMAX) { candD[rowB * CMAX + s] = d0B; candC[rowB * CMAX + s] = (u32)c; } }
                if (d1B <= thB) { u32 s = atomicAdd(&cnt_s[rowB], 1u); if (s < CMAX) { candD[rowB * CMAX + s] = d1B; candC[rowB * CMAX + s] = (u32)(c + 1); } }
            }
        }
    }

    __syncthreads();   // phase-1 complete: bestB/cand/cnt final

    // ---- phase-2: candidate set provably contains the exact winner.
    //      cnt==1  -> that candidate IS the winner (no rescore needed).
    //      2..CMAX -> exact fp32 rescore of the candidates.
    //      >CMAX   -> full 512-code fp32 rescan (overflow fallback).
    for (int i = 0; i < 8; ++i) {
        int px = wid * 8 + i;
        u32 c = cnt_s[px];
        if (c == 1) {
            if (lane == 0) fidx[px] = candC[px * CMAX];
        } else if (c <= CMAX) {
            float M = KEPS * sqrtf(znorm[px] * emax2);
            float th = unfkey(bestB[px]) + 2.f * M;
            ull best = ~0ull;
            for (u32 j = 0; j < c; ++j) {
                if (candD[px * CMAX + j] <= th) {
                    u32 cc = candC[px * CMAX + j];
                    float d = hh_s[cc] - rescore_dot(ZH, ZL, emb, px, (int)cc, lane);
                    ull key = ((ull)fkey(d) << 32) | cc;
                    if (key < best) best = key;
                }
            }
            if (lane == 0) fidx[px] = (u32)best;
        } else {
            ull best = ~0ull;
            for (int cc = 0; cc < 512; ++cc) {
                float d = hh_s[cc] - rescore_dot(ZH, ZL, emb, px, cc, lane);
                ull key = ((ull)fkey(d) << 32) | (u32)cc;
                if (key < best) best = key;
            }
            if (lane == 0) fidx[px] = (u32)best;
        }
    }

    __syncthreads();   // fidx final; Z planes reusable as gather staging

    // ---- gather winning rows into Qs[c][px], then coalesced write ----
    {
        int px = tid >> 2, qu = tid & 3;
        u32 idx = fidx[px];
        const float* er = emb + (size_t)idx * 128 + 32 * qu;
        float* Qs = SMF;
        #pragma unroll
        for (int i = 0; i < 8; ++i) {
            float4 v = *(const float4*)(er + 4 * i);
            int c = 32 * qu + 4 * i;
            Qs[(c + 0) * QS_STRIDE + px] = v.x;
            Qs[(c + 1) * QS_STRIDE + px] = v.y;
            Qs[(c + 2) * QS_STRIDE + px] = v.z;
            Qs[(c + 3) * QS_STRIDE + px] = v.w;
        }
    }
    __syncthreads();
    {
        int r = tid >> 1, half = tid & 1;           // 128 ch x 2 halves of 32px
        float* orow = out + (size_t)b * 128 * 4096 + (size_t)r * 4096 + p0 + 32 * half;
        const float* qrow = SMF + r * QS_STRIDE + 32 * half;
        #pragma unroll
        for (int i = 0; i < 8; ++i)
            *(float4*)(orow + 4 * i) = *(const float4*)(qrow + 4 * i);
    }
}

extern "C" void kernel_launch(void* const* d_in, const int* in_sizes, int n_in,
                              void* d_out, int out_size) {
    const float* z   = (const float*)d_in[0];   // (32,128,64,64) fp32
    const float* emb = (const float*)d_in[1];   // (512,128) fp32
    float* out = (float*)d_out;

    cudaFuncSetAttribute(vq_mma_kernel,
                         cudaFuncAttributeMaxDynamicSharedMemorySize, SMEM_BYTES);

    vq_prep<<<64, 256>>>(emb);
    vq_mma_kernel<<<2048, 256, SMEM_BYTES>>>(z, emb, out);
}

// round 16
// speedup vs baseline: 1.7082x; 1.1031x over previous
#include <cuda_runtime.h>
#include <cuda_fp16.h>
#include <cstdint>

typedef unsigned long long ull;
typedef unsigned int u32;

// ---------------- global scratch (static, no allocs) ----------------
// Bh fragment image for direct LDG.128:
//   uint4 index: (((ks*2+h)*4+cg)*4+np)*32 + lane   (lane = q*4+jj)
__device__ __align__(16) u32 g_EimgH[32768];     // 128KB
__device__ float g_hhalf[512];     // 0.5*||e_c||^2 (fp32)
__device__ int g_emax2bits;        // max ||e_c||^2 as float bits (zero-init)

#define KEPS 1.25e-3f
#define CMAX 16
#define ZRS 144                    // Z plane row stride (u32); 32 rows per plane

__device__ __forceinline__ u32 packsplit_hi(float v0, float v1, float& r0, float& r1) {
    __half h0 = __float2half_rn(v0), h1 = __float2half_rn(v1);
    r0 = v0 - __half2float(h0);
    r1 = v1 - __half2float(h1);
    return (u32)__half_as_ushort(h0) | ((u32)__half_as_ushort(h1) << 16);
}
__device__ __forceinline__ u32 pack_lo(float r0, float r1) {
    __half l0 = __float2half_rn(r0), l1 = __float2half_rn(r1);
    return (u32)__half_as_ushort(l0) | ((u32)__half_as_ushort(l1) << 16);
}
__device__ __forceinline__ unsigned fkey(float f) {   // monotonic float->uint
    unsigned u = __float_as_uint(f);
    return (u & 0x80000000u) ? ~u : (u | 0x80000000u);
}
__device__ __forceinline__ float unfkey(u32 k) {
    u32 u = (k & 0x80000000u) ? (k & 0x7fffffffu) : ~k;
    return __uint_as_float(u);
}
__device__ __forceinline__ void mma16(float* c, u32 a0, u32 a1, u32 a2, u32 a3,
                                      u32 b0, u32 b1) {
    asm("mma.sync.aligned.m16n8k16.row.col.f32.f16.f16.f32 "
        "{%0,%1,%2,%3}, {%4,%5,%6,%7}, {%8,%9}, {%0,%1,%2,%3};"
        : "+f"(c[0]), "+f"(c[1]), "+f"(c[2]), "+f"(c[3])
        : "r"(a0), "r"(a1), "r"(a2), "r"(a3), "r"(b0), "r"(b1));
}

// ---------------- prep: n-paired Bh fragment image + norms ----------------
// Launch: 64 blocks x 256 threads (16384 threads).
//   Norms: warp per code (512 warps), lane-parallel float4 + shfl reduce.
//   Scatter: 2 (code,kpair) items per thread.
__global__ void vq_prep(const float* __restrict__ emb) {
    int t = blockIdx.x * blockDim.x + threadIdx.x;
    int lane = t & 31, code_w = t >> 5;            // warp id = code

    // ---- norms: each lane loads one float4 of the 128-float row ----
    {
        const float4* row4 = (const float4*)(emb + (size_t)code_w * 128);
        float4 v = row4[lane];
        float s = v.x * v.x + v.y * v.y + v.z * v.z + v.w * v.w;
        #pragma unroll
        for (int d = 16; d; d >>= 1) s += __shfl_xor_sync(0xffffffffu, s, d);
        if (lane == 0) {
            g_hhalf[code_w] = 0.5f * s;
            atomicMax(&g_emax2bits, __float_as_int(s));
        }
    }

    // ---- fragment scatter: 2 items per thread ----
    #pragma unroll
    for (int it = 0; it < 2; ++it) {
        int i = t + it * 16384;                    // (code, kpair)
        int code = i >> 6, p = i & 63;
        float2 v2 = *(const float2*)(emb + (size_t)code * 128 + 2 * p);
        float r0, r1;
        u32 hi = packsplit_hi(v2.x, v2.y, r0, r1);
        int ks = p >> 3, pp = p & 7, jj = pp & 3, s = pp >> 2;
        int h = code >> 8, c8 = code & 255;
        int cg = c8 >> 6, rem = c8 & 63, n = rem >> 3, q = rem & 7;
        int np = n >> 1, no = n & 1;
        int idx = ((((ks * 2 + h) * 4 + cg) * 4 + np) * 32 + q * 4 + jj) * 4 + no * 2 + s;
        g_EimgH[idx] = hi;
    }
}

// ---------------- main kernel (round-12 verified form) ----------------
// Z plane layout (pair-interleaved, mma-ordered quads):
//   row r = (px>>4)*8 + (px&7), s = (px>>3)&1.
//   quad j of k-group ks holds kpairs {ks*8+j, ks*8+j+4}:
//     uint4 = [Z(px_a, j), Z(px_b, j), Z(px_a, j+4), Z(px_b, j+4)]
//   at u32 pos: r*ZRS + (ks*4 + ((j + (r>>1)) & 3))*4 + half*2 + s
#define ZHOFF  0          // 32 x 144
#define ZLOFF  4608       // 32 x 144
#define HHOFF  9216       // 512 floats
#define ZNOFF  9728       // 64 floats
#define BSTOFF 9792       // 64 u32 (fkey bits)
#define CDOFF  9856       // 64 x 16 floats
#define CCOFF  10880      // 64 x 16 u32
#define CNTOFF 11904      // 64 u32
#define FIOFF  11968      // 64 u32
#define SMEM_BYTES (12032 * 4)
#define QS_STRIDE 68

__device__ __forceinline__ u32 zpos(int px, int p) {   // u32 index within a plane
    int r = (px >> 4) * 8 + (px & 7), s = (px >> 3) & 1;
    int ks = p >> 3, c = p & 7;
    return (u32)(r * ZRS + (ks * 4 + (((c & 3) + (r >> 1)) & 3)) * 4 + (c >> 2) * 2 + s);
}

__device__ __forceinline__ float rescore_dot(const u32* __restrict__ ZH,
                                             const u32* __restrict__ ZL,
                                             const float* __restrict__ emb,
                                             int px, int cc, int lane) {
    int p0 = 2 * lane, p1 = p0 + 1;
    u32 o0 = zpos(px, p0), o1 = zpos(px, p1);
    float2 a0 = __half22float2(*(const __half2*)&ZH[o0]);
    float2 b0 = __half22float2(*(const __half2*)&ZL[o0]);
    float2 a1 = __half22float2(*(const __half2*)&ZH[o1]);
    float2 b1 = __half22float2(*(const __half2*)&ZL[o1]);
    float4 e = *(const float4*)(emb + (size_t)cc * 128 + 4 * lane);
    float part = (a0.x + b0.x) * e.x + (a0.y + b0.y) * e.y
               + (a1.x + b1.x) * e.z + (a1.y + b1.y) * e.w;
    #pragma unroll
    for (int d = 16; d; d >>= 1) part += __shfl_xor_sync(0xffffffffu, part, d);
    return part;
}

__global__ __launch_bounds__(256, 2)
void vq_mma_kernel(const float* __restrict__ z, const float* __restrict__ emb,
                   float* __restrict__ out) {
    extern __shared__ float SMF[];
    u32* ZU = (u32*)SMF;
    const u32* ZH = ZU + ZHOFF;
    const u32* ZL = ZU + ZLOFF;
    float* hh_s = SMF + HHOFF;
    float* znorm = SMF + ZNOFF;
    u32* bestB = ZU + BSTOFF;
    float* candD = SMF + CDOFF;
    u32* candC = ZU + CCOFF;
    u32* cnt_s = ZU + CNTOFF;
    u32* fidx = ZU + FIOFF;

    const int tid = threadIdx.x;
    const int wid = tid >> 5, lane = tid & 31;
    const int jj = lane & 3, q = lane >> 2;
    const int pg = wid & 1, cg = wid >> 1;          // 2 px-groups x 4 code-groups
    const int px0 = pg << 5;
    const int b = blockIdx.x >> 6;
    const int p0 = (blockIdx.x & 63) << 6;          // 64-px tile

    const float* zb = z + (size_t)b * 128 * 4096 + p0;

    hh_s[tid] = g_hhalf[tid];
    hh_s[tid + 256] = g_hhalf[tid + 256];
    if (tid < 64) { bestB[tid] = 0xFFFFFFFFu; znorm[tid] = 0.f; cnt_s[tid] = 0u; }
    __syncthreads();

    // ---- Z producer: thread = (row r, k-group kg); wide STS.128 writes ----
    {
        int r = tid & 31, kg = tid >> 5;
        int px_a = (r >> 3) * 16 + (r & 7);         // s = 0
        int px_b = px_a + 8;                        // s = 1
        u32 hiA[8], loA[8], hiB[8], loB[8];
        float sa = 0.f, sb = 0.f;
        #pragma unroll
        for (int c = 0; c < 8; ++c) {               // kpair p = kg*8+c
            const float* zc = zb + (size_t)(kg * 8 + c) * 2 * 4096;
            float va0 = zc[px_a], va1 = zc[4096 + px_a];
            float vb0 = zc[px_b], vb1 = zc[4096 + px_b];
            float r0, r1;
            hiA[c] = packsplit_hi(va0, va1, r0, r1);
            loA[c] = pack_lo(r0, r1);
            sa += va0 * va0 + va1 * va1;
            hiB[c] = packsplit_hi(vb0, vb1, r0, r1);
            loB[c] = pack_lo(r0, r1);
            sb += vb0 * vb0 + vb1 * vb1;
        }
        u32* Zh = ZU + ZHOFF + r * ZRS;
        u32* Zl = ZU + ZLOFF + r * ZRS;
        int rs = r >> 1;
        #pragma unroll
        for (int j = 0; j < 4; ++j) {               // quad j: kpairs {j, j+4}
            int pq = (kg * 4 + ((j + rs) & 3)) * 4;
            *(uint4*)(Zh + pq) = make_uint4(hiA[j], hiB[j], hiA[j + 4], hiB[j + 4]);
            *(uint4*)(Zl + pq) = make_uint4(loA[j], loB[j], loA[j + 4], loB[j + 4]);
        }
        atomicAdd(&znorm[px_a], sa);
        atomicAdd(&znorm[px_b], sb);
    }
    __syncthreads();

    const float emax2 = __int_as_float(g_emax2bits);
    const u32* Arow0 = ZH + ((pg * 2 + 0) * 8 + q) * ZRS;   // m=0: px0+q / px0+q+8
    const u32* Arow1 = ZH + ((pg * 2 + 1) * 8 + q) * ZRS;   // m=1: px0+16+q / +24
    const int qsw = (q >> 1) & 3;

    for (int h = 0; h < 2; ++h) {
        float acc[2][8][4];
        #pragma unroll
        for (int m = 0; m < 2; ++m)
            #pragma unroll
            for (int n = 0; n < 8; ++n)
                #pragma unroll
                for (int r = 0; r < 4; ++r) acc[m][n][r] = 0.f;

        #pragma unroll
        for (int ks = 0; ks < 8; ++ks) {
            int pq = (ks * 4 + ((jj + qsw) & 3)) * 4;
            uint4 A0 = *(const uint4*)(Arow0 + pq);   // [a0 a1 a2 a3] mma order
            uint4 A1 = *(const uint4*)(Arow1 + pq);
            const uint4* e4 = (const uint4*)g_EimgH
                              + (size_t)(((ks * 2 + h) * 4 + cg) * 4) * 32 + lane;
            #pragma unroll
            for (int np = 0; np < 4; ++np) {
                uint4 B = __ldg(e4 + np * 32);
                mma16(acc[0][2 * np],     A0.x, A0.y, A0.z, A0.w, B.x, B.y);
                mma16(acc[1][2 * np],     A1.x, A1.y, A1.z, A1.w, B.x, B.y);
                mma16(acc[0][2 * np + 1], A0.x, A0.y, A0.z, A0.w, B.z, B.w);
                mma16(acc[1][2 * np + 1], A1.x, A1.y, A1.z, A1.w, B.z, B.w);
            }
        }

        // ---- phase-1 epilogue: float-only min + candidate collection ----
        #pragma unroll
        for (int m = 0; m < 2; ++m) {
            int rowA = px0 + 16 * m + q, rowB = rowA + 8;
            float mnA = 1e30f, mnB = 1e30f;
            #pragma unroll
            for (int n = 0; n < 8; ++n) {
                int c = h * 256 + cg * 64 + 8 * n + 2 * jj;
                float hc0 = hh_s[c], hc1 = hh_s[c + 1];
                mnA = fminf(mnA, fminf(hc0 - acc[m][n][0], hc1 - acc[m][n][1]));
                mnB = fminf(mnB, fminf(hc0 - acc[m][n][2], hc1 - acc[m][n][3]));
            }
            #pragma unroll
            for (int d = 1; d <= 2; d <<= 1) {
                mnA = fminf(mnA, __shfl_xor_sync(0xffffffffu, mnA, d));
                mnB = fminf(mnB, __shfl_xor_sync(0xffffffffu, mnB, d));
            }
            u32 kA = fkey(mnA), kB = fkey(mnB);
            u32 curA = *(volatile u32*)&bestB[rowA];
            u32 curB = *(volatile u32*)&bestB[rowB];
            float MA = KEPS * sqrtf(znorm[rowA] * emax2);
            float MB = KEPS * sqrtf(znorm[rowB] * emax2);
            float thA = unfkey(kA < curA ? kA : curA) + 2.f * MA;
            float thB = unfkey(kB < curB ? kB : curB) + 2.f * MB;
            if (jj == 0) {
                atomicMin(&bestB[rowA], kA);
                atomicMin(&bestB[rowB], kB);
            }
            #pragma unroll
            for (int n = 0; n < 8; ++n) {
                int c = h * 256 + cg * 64 + 8 * n + 2 * jj;
                float hc0 = hh_s[c], hc1 = hh_s[c + 1];
                float d0A = hc0 - acc[m][n][0], d1A = hc1 - acc[m][n][1];
                float d0B = hc0 - acc[m][n][2], d1B = hc1 - acc[m][n][3];
                if (d0A <= thA) { u32 s = atomicAdd(&cnt_s[rowA], 1u); if (s < CMAX) { candD[rowA * CMAX + s] = d0A; candC[rowA * CMAX + s] = (u32)c; } }
                if (d1A <= thA) { u32 s = atomicAdd(&cnt_s[rowA], 1u); if (s < CMAX) { candD[rowA * CMAX + s] = d1A; candC[rowA * CMAX + s] = (u32)(c + 1); } }
                if (d0B <= thB) { u32 s = atomicAdd(&cnt_s[rowB], 1u); if (s < CMAX) { candD[rowB * CMAX + s] = d0B; candC[rowB * CMAX + s] = (u32)c; } }
                if (d1B <= thB) { u32 s = atomicAdd(&cnt_s[rowB], 1u); if (s < CMAX) { candD[rowB * CMAX + s] = d1B; candC[rowB * CMAX + s] = (u32)(c + 1); } }
            }
        }
    }

    __syncthreads();   // phase-1 complete: bestB/cand/cnt final

    // ---- phase-2: exact fp32 rescore of candidates (warp w -> 8 pixels) ----
    for (int i = 0; i < 8; ++i) {
        int px = wid * 8 + i;
        u32 c = cnt_s[px];
        float M = KEPS * sqrtf(znorm[px] * emax2);
        float th = unfkey(bestB[px]) + 2.f * M;
        ull best = ~0ull;
        if (c <= CMAX) {
            for (u32 j = 0; j < c; ++j) {
                if (candD[px * CMAX + j] <= th) {
                    u32 cc = candC[px * CMAX + j];
                    float d = hh_s[cc] - rescore_dot(ZH, ZL, emb, px, (int)cc, lane);
                    ull key = ((ull)fkey(d) << 32) | cc;
                    if (key < best) best = key;
                }
            }
        } else {
            for (int cc = 0; cc < 512; ++cc) {      // overflow fallback: full rescan
                float d = hh_s[cc] - rescore_dot(ZH, ZL, emb, px, cc, lane);
                ull key = ((ull)fkey(d) << 32) | (u32)cc;
                if (key < best) best = key;
            }
        }
        if (lane == 0) fidx[px] = (u32)best;
    }

    __syncthreads();   // fidx final; Z planes reusable as gather staging

    // ---- gather winning rows into Qs[c][px], then coalesced write ----
    {
        int px = tid >> 2, qu = tid & 3;
        u32 idx = fidx[px];
        const float* er = emb + (size_t)idx * 128 + 32 * qu;
        float* Qs = SMF;
        #pragma unroll
        for (int i = 0; i < 8; ++i) {
            float4 v = *(const float4*)(er + 4 * i);
            int c = 32 * qu + 4 * i;
            Qs[(c + 0) * QS_STRIDE + px] = v.x;
            Qs[(c + 1) * QS_STRIDE + px] = v.y;
            Qs[(c + 2) * QS_STRIDE + px] = v.z;
            Qs[(c + 3) * QS_STRIDE + px] = v.w;
        }
    }
    __syncthreads();
    {
        int r = tid >> 1, half = tid & 1;           // 128 ch x 2 halves of 32px
        float* orow = out + (size_t)b * 128 * 4096 + (size_t)r * 4096 + p0 + 32 * half;
        const float* qrow = SMF + r * QS_STRIDE + 32 * half;
        #pragma unroll
        for (int i = 0; i < 8; ++i)
            *(float4*)(orow + 4 * i) = *(const float4*)(qrow + 4 * i);
    }
}

extern "C" void kernel_launch(void* const* d_in, const int* in_sizes, int n_in,
                              void* d_out, int out_size) {
    const float* z   = (const float*)d_in[0];   // (32,128,64,64) fp32
    const float* emb = (const float*)d_in[1];   // (512,128) fp32
    float* out = (float*)d_out;

    cudaFuncSetAttribute(vq_mma_kernel,
                         cudaFuncAttributeMaxDynamicSharedMemorySize, SMEM_BYTES);

    vq_prep<<<64, 256>>>(emb);
    vq_mma_kernel<<<2048, 256, SMEM_BYTES>>>(z, emb, out);
}

// round 17
// speedup vs baseline: 1.7344x; 1.0153x over previous
#include <cuda_runtime.h>
#include <cuda_fp16.h>
#include <cstdint>

typedef unsigned long long ull;
typedef unsigned int u32;

// ---------------- global scratch (static, no allocs) ----------------
// Bh fragment image for direct LDG.128:
//   uint4 index: (((ks*2+h)*4+cg)*4+np)*32 + lane   (lane = q*4+jj)
__device__ __align__(16) u32 g_EimgH[32768];     // 128KB
__device__ float g_hhalf[512];     // 0.5*||e_c||^2 (fp32)
__device__ int g_emax2bits;        // max ||e_c||^2 as float bits (zero-init)

#define KEPS 1.25e-3f
#define CMAX 16
#define ZRS 144                    // Z plane row stride (u32); 32 rows per plane

__device__ __forceinline__ u32 packsplit_hi(float v0, float v1, float& r0, float& r1) {
    __half h0 = __float2half_rn(v0), h1 = __float2half_rn(v1);
    r0 = v0 - __half2float(h0);
    r1 = v1 - __half2float(h1);
    return (u32)__half_as_ushort(h0) | ((u32)__half_as_ushort(h1) << 16);
}
__device__ __forceinline__ u32 pack_lo(float r0, float r1) {
    __half l0 = __float2half_rn(r0), l1 = __float2half_rn(r1);
    return (u32)__half_as_ushort(l0) | ((u32)__half_as_ushort(l1) << 16);
}
__device__ __forceinline__ unsigned fkey(float f) {   // monotonic float->uint
    unsigned u = __float_as_uint(f);
    return (u & 0x80000000u) ? ~u : (u | 0x80000000u);
}
__device__ __forceinline__ float unfkey(u32 k) {
    u32 u = (k & 0x80000000u) ? (k & 0x7fffffffu) : ~k;
    return __uint_as_float(u);
}
__device__ __forceinline__ void mma16(float* c, u32 a0, u32 a1, u32 a2, u32 a3,
                                      u32 b0, u32 b1) {
    asm("mma.sync.aligned.m16n8k16.row.col.f32.f16.f16.f32 "
        "{%0,%1,%2,%3}, {%4,%5,%6,%7}, {%8,%9}, {%0,%1,%2,%3};"
        : "+f"(c[0]), "+f"(c[1]), "+f"(c[2]), "+f"(c[3])
        : "r"(a0), "r"(a1), "r"(a2), "r"(a3), "r"(b0), "r"(b1));
}

// ---------------- prep: warp-parallel norms + fragment scatter ----------------
__global__ void vq_prep(const float* __restrict__ emb) {
    int t = blockIdx.x * blockDim.x + threadIdx.x;
    int lane = t & 31, code_w = t >> 5;            // warp id = code

    // ---- norms: each lane loads one float4 of the 128-float row ----
    {
        const float4* row4 = (const float4*)(emb + (size_t)code_w * 128);
        float4 v = row4[lane];
        float s = v.x * v.x + v.y * v.y + v.z * v.z + v.w * v.w;
        #pragma unroll
        for (int d = 16; d; d >>= 1) s += __shfl_xor_sync(0xffffffffu, s, d);
        if (lane == 0) {
            g_hhalf[code_w] = 0.5f * s;
            atomicMax(&g_emax2bits, __float_as_int(s));
        }
    }

    // ---- fragment scatter: 2 items per thread ----
    #pragma unroll
    for (int it = 0; it < 2; ++it) {
        int i = t + it * 16384;                    // (code, kpair)
        int code = i >> 6, p = i & 63;
        float2 v2 = *(const float2*)(emb + (size_t)code * 128 + 2 * p);
        float r0, r1;
        u32 hi = packsplit_hi(v2.x, v2.y, r0, r1);
        int ks = p >> 3, pp = p & 7, jj = pp & 3, s = pp >> 2;
        int h = code >> 8, c8 = code & 255;
        int cg = c8 >> 6, rem = c8 & 63, n = rem >> 3, q = rem & 7;
        int np = n >> 1, no = n & 1;
        int idx = ((((ks * 2 + h) * 4 + cg) * 4 + np) * 32 + q * 4 + jj) * 4 + no * 2 + s;
        g_EimgH[idx] = hi;
    }
}

// ---------------- main kernel ----------------
// Z plane layout (pair-interleaved, mma-ordered quads) — see round 12.
#define ZHOFF  0          // 32 x 144
#define ZLOFF  4608       // 32 x 144
#define HHOFF  9216       // 512 floats
#define ZNOFF  9728       // 64 floats
#define BSTOFF 9792       // 64 u32 (fkey bits)
#define CDOFF  9856       // 64 x 16 floats
#define CCOFF  10880      // 64 x 16 u32
#define CNTOFF 11904      // 64 u32
#define FIOFF  11968      // 64 u32
#define SMEM_BYTES (12032 * 4)
#define QS_STRIDE 68

__device__ __forceinline__ u32 zpos(int px, int p) {   // u32 index within a plane
    int r = (px >> 4) * 8 + (px & 7), s = (px >> 3) & 1;
    int ks = p >> 3, c = p & 7;
    return (u32)(r * ZRS + (ks * 4 + (((c & 3) + (r >> 1)) & 3)) * 4 + (c >> 2) * 2 + s);
}

__device__ __forceinline__ float rescore_dot(const u32* __restrict__ ZH,
                                             const u32* __restrict__ ZL,
                                             const float* __restrict__ emb,
                                             int px, int cc, int lane) {
    int p0 = 2 * lane, p1 = p0 + 1;
    u32 o0 = zpos(px, p0), o1 = zpos(px, p1);
    float2 a0 = __half22float2(*(const __half2*)&ZH[o0]);
    float2 b0 = __half22float2(*(const __half2*)&ZL[o0]);
    float2 a1 = __half22float2(*(const __half2*)&ZH[o1]);
    float2 b1 = __half22float2(*(const __half2*)&ZL[o1]);
    float4 e = *(const float4*)(emb + (size_t)cc * 128 + 4 * lane);
    float part = (a0.x + b0.x) * e.x + (a0.y + b0.y) * e.y
               + (a1.x + b1.x) * e.z + (a1.y + b1.y) * e.w;
    #pragma unroll
    for (int d = 16; d; d >>= 1) part += __shfl_xor_sync(0xffffffffu, part, d);
    return part;
}

__global__ __launch_bounds__(256, 2)
void vq_mma_kernel(const float* __restrict__ z, const float* __restrict__ emb,
                   float* __restrict__ out) {
    extern __shared__ float SMF[];
    u32* ZU = (u32*)SMF;
    const u32* ZH = ZU + ZHOFF;
    const u32* ZL = ZU + ZLOFF;
    float* hh_s = SMF + HHOFF;
    float* znorm = SMF + ZNOFF;
    u32* bestB = ZU + BSTOFF;
    float* candD = SMF + CDOFF;
    u32* candC = ZU + CCOFF;
    u32* cnt_s = ZU + CNTOFF;
    u32* fidx = ZU + FIOFF;

    const int tid = threadIdx.x;
    const int wid = tid >> 5, lane = tid & 31;
    const int jj = lane & 3, q = lane >> 2;
    const int pg = wid & 1, cg = wid >> 1;          // 2 px-groups x 4 code-groups
    const int px0 = pg << 5;
    const int b = blockIdx.x >> 6;
    const int p0 = (blockIdx.x & 63) << 6;          // 64-px tile

    const float* zb = z + (size_t)b * 128 * 4096 + p0;

    hh_s[tid] = g_hhalf[tid];
    hh_s[tid + 256] = g_hhalf[tid + 256];
    if (tid < 64) { bestB[tid] = 0xFFFFFFFFu; znorm[tid] = 0.f; cnt_s[tid] = 0u; }
    __syncthreads();

    // ---- Z producer: thread = (row r, k-group kg); wide STS.128 writes ----
    {
        int r = tid & 31, kg = tid >> 5;
        int px_a = (r >> 3) * 16 + (r & 7);         // s = 0
        int px_b = px_a + 8;                        // s = 1
        u32 hiA[8], loA[8], hiB[8], loB[8];
        float sa = 0.f, sb = 0.f;
        #pragma unroll
        for (int c = 0; c < 8; ++c) {               // kpair p = kg*8+c
            const float* zc = zb + (size_t)(kg * 8 + c) * 2 * 4096;
            float va0 = zc[px_a], va1 = zc[4096 + px_a];
            float vb0 = zc[px_b], vb1 = zc[4096 + px_b];
            float r0, r1;
            hiA[c] = packsplit_hi(va0, va1, r0, r1);
            loA[c] = pack_lo(r0, r1);
            sa += va0 * va0 + va1 * va1;
            hiB[c] = packsplit_hi(vb0, vb1, r0, r1);
            loB[c] = pack_lo(r0, r1);
            sb += vb0 * vb0 + vb1 * vb1;
        }
        u32* Zh = ZU + ZHOFF + r * ZRS;
        u32* Zl = ZU + ZLOFF + r * ZRS;
        int rs = r >> 1;
        #pragma unroll
        for (int j = 0; j < 4; ++j) {               // quad j: kpairs {j, j+4}
            int pq = (kg * 4 + ((j + rs) & 3)) * 4;
            *(uint4*)(Zh + pq) = make_uint4(hiA[j], hiB[j], hiA[j + 4], hiB[j + 4]);
            *(uint4*)(Zl + pq) = make_uint4(loA[j], loB[j], loA[j + 4], loB[j + 4]);
        }
        atomicAdd(&znorm[px_a], sa);
        atomicAdd(&znorm[px_b], sb);
    }
    __syncthreads();

    const float emax2 = __int_as_float(g_emax2bits);
    const u32* Arow0 = ZH + ((pg * 2 + 0) * 8 + q) * ZRS;   // m=0: px0+q / px0+q+8
    const u32* Arow1 = ZH + ((pg * 2 + 1) * 8 + q) * ZRS;   // m=1: px0+16+q / +24
    const int qsw = (q >> 1) & 3;

    // ---- B register double-buffer: prologue load (h=0, ks=0) ----
    uint4 Bb0[4], Bb1[4];
    {
        const uint4* e4 = (const uint4*)g_EimgH + (size_t)(cg * 4) * 32 + lane;
        #pragma unroll
        for (int np = 0; np < 4; ++np) Bb0[np] = __ldg(e4 + np * 32);
    }

    for (int h = 0; h < 2; ++h) {
        float acc[2][8][4];
        #pragma unroll
        for (int m = 0; m < 2; ++m)
            #pragma unroll
            for (int n = 0; n < 8; ++n)
                #pragma unroll
                for (int r = 0; r < 4; ++r) acc[m][n][r] = 0.f;

        #pragma unroll
        for (int ks = 0; ks < 8; ++ks) {
            // prefetch next (h,ks) into the alternate buffer (overlaps mma below;
            // the h-boundary load is covered by the phase-1 epilogue)
            uint4* nxt = (ks & 1) ? Bb0 : Bb1;
            if (ks < 7 || h == 0) {
                int nh = (ks < 7) ? h : 1, nks = (ks < 7) ? (ks + 1) : 0;
                const uint4* e4n = (const uint4*)g_EimgH
                                   + (size_t)(((nks * 2 + nh) * 4 + cg) * 4) * 32 + lane;
                #pragma unroll
                for (int np = 0; np < 4; ++np) nxt[np] = __ldg(e4n + np * 32);
            }
            const uint4* B = (ks & 1) ? Bb1 : Bb0;
            int pq = (ks * 4 + ((jj + qsw) & 3)) * 4;
            uint4 A0 = *(const uint4*)(Arow0 + pq);   // [a0 a1 a2 a3] mma order
            uint4 A1 = *(const uint4*)(Arow1 + pq);
            #pragma unroll
            for (int np = 0; np < 4; ++np) {
                mma16(acc[0][2 * np],     A0.x, A0.y, A0.z, A0.w, B[np].x, B[np].y);
                mma16(acc[1][2 * np],     A1.x, A1.y, A1.z, A1.w, B[np].x, B[np].y);
                mma16(acc[0][2 * np + 1], A0.x, A0.y, A0.z, A0.w, B[np].z, B[np].w);
                mma16(acc[1][2 * np + 1], A1.x, A1.y, A1.z, A1.w, B[np].z, B[np].w);
            }
        }

        // ---- phase-1 epilogue: float-only min + candidate collection ----
        #pragma unroll
        for (int m = 0; m < 2; ++m) {
            int rowA = px0 + 16 * m + q, rowB = rowA + 8;
            float mnA = 1e30f, mnB = 1e30f;
            #pragma unroll
            for (int n = 0; n < 8; ++n) {
                int c = h * 256 + cg * 64 + 8 * n + 2 * jj;
                float hc0 = hh_s[c], hc1 = hh_s[c + 1];
                mnA = fminf(mnA, fminf(hc0 - acc[m][n][0], hc1 - acc[m][n][1]));
                mnB = fminf(mnB, fminf(hc0 - acc[m][n][2], hc1 - acc[m][n][3]));
            }
            #pragma unroll
            for (int d = 1; d <= 2; d <<= 1) {
                mnA = fminf(mnA, __shfl_xor_sync(0xffffffffu, mnA, d));
                mnB = fminf(mnB, __shfl_xor_sync(0xffffffffu, mnB, d));
            }
            u32 kA = fkey(mnA), kB = fkey(mnB);
            u32 curA = *(volatile u32*)&bestB[rowA];
            u32 curB = *(volatile u32*)&bestB[rowB];
            float MA = KEPS * sqrtf(znorm[rowA] * emax2);
            float MB = KEPS * sqrtf(znorm[rowB] * emax2);
            float thA = unfkey(kA < curA ? kA : curA) + 2.f * MA;
            float thB = unfkey(kB < curB ? kB : curB) + 2.f * MB;
            if (jj == 0) {
                atomicMin(&bestB[rowA], kA);
                atomicMin(&bestB[rowB], kB);
            }
            #pragma unroll
            for (int n = 0; n < 8; ++n) {
                int c = h * 256 + cg * 64 + 8 * n + 2 * jj;
                float hc0 = hh_s[c], hc1 = hh_s[c + 1];
                float d0A = hc0 - acc[m][n][0], d1A = hc1 - acc[m][n][1];
                float d0B = hc0 - acc[m][n][2], d1B = hc1 - acc[m][n][3];
                if (d0A <= thA) { u32 s = atomicAdd(&cnt_s[rowA], 1u); if (s < CMAX) { candD[rowA * CMAX + s] = d0A; candC[rowA * CMAX + s] = (u32)c; } }
                if (d1A <= thA) { u32 s = atomicAdd(&cnt_s[rowA], 1u); if (s < CMAX) { candD[rowA * CMAX + s] = d1A; candC[rowA * CMAX + s] = (u32)(c + 1); } }
                if (d0B <= thB) { u32 s = atomicAdd(&cnt_s[rowB], 1u); if (s < CMAX) { candD[rowB * CMAX + s] = d0B; candC[rowB * CMAX + s] = (u32)c; } }
                if (d1B <= thB) { u32 s = atomicAdd(&cnt_s[rowB], 1u); if (s < CMAX) { candD[rowB * CMAX + s] = d1B; candC[rowB * CMAX + s] = (u32)(c + 1); } }
            }
        }
    }

    __syncthreads();   // phase-1 complete: bestB/cand/cnt final

    // ---- phase-2: exact fp32 rescore of candidates (warp w -> 8 pixels) ----
    for (int i = 0; i < 8; ++i) {
        int px = wid * 8 + i;
        u32 c = cnt_s[px];
        float M = KEPS * sqrtf(znorm[px] * emax2);
        float th = unfkey(bestB[px]) + 2.f * M;
        ull best = ~0ull;
        if (c <= CMAX) {
            for (u32 j = 0; j < c; ++j) {
                if (candD[px * CMAX + j] <= th) {
                    u32 cc = candC[px * CMAX + j];
                    float d = hh_s[cc] - rescore_dot(ZH, ZL, emb, px, (int)cc, lane);
                    ull key = ((ull)fkey(d) << 32) | cc;
                    if (key < best) best = key;
                }
            }
        } else {
            for (int cc = 0; cc < 512; ++cc) {      // overflow fallback: full rescan
                float d = hh_s[cc] - rescore_dot(ZH, ZL, emb, px, cc, lane);
                ull key = ((ull)fkey(d) << 32) | (u32)cc;
                if (key < best) best = key;
            }
        }
        if (lane == 0) fidx[px] = (u32)best;
    }

    __syncthreads();   // fidx final; Z planes reusable as gather staging

    // ---- gather winning rows into Qs[c][px], then coalesced write ----
    {
        int px = tid >> 2, qu = tid & 3;
        u32 idx = fidx[px];
        const float* er = emb + (size_t)idx * 128 + 32 * qu;
        float* Qs = SMF;
        #pragma unroll
        for (int i = 0; i < 8; ++i) {
            float4 v = *(const float4*)(er + 4 * i);
            int c = 32 * qu + 4 * i;
            Qs[(c + 0) * QS_STRIDE + px] = v.x;
            Qs[(c + 1) * QS_STRIDE + px] = v.y;
            Qs[(c + 2) * QS_STRIDE + px] = v.z;
            Qs[(c + 3) * QS_STRIDE + px] = v.w;
        }
    }
    __syncthreads();
    {
        int r = tid >> 1, half = tid & 1;           // 128 ch x 2 halves of 32px
        float* orow = out + (size_t)b * 128 * 4096 + (size_t)r * 4096 + p0 + 32 * half;
        const float* qrow = SMF + r * QS_STRIDE + 32 * half;
        #pragma unroll
        for (int i = 0; i < 8; ++i)
            *(float4*)(orow + 4 * i) = *(const float4*)(qrow + 4 * i);
    }
}

extern "C" void kernel_launch(void* const* d_in, const int* in_sizes, int n_in,
                              void* d_out, int out_size) {
    const float* z   = (const float*)d_in[0];   // (32,128,64,64) fp32
    const float* emb = (const float*)d_in[1];   // (512,128) fp32
    float* out = (float*)d_out;

    cudaFuncSetAttribute(vq_mma_kernel,
                         cudaFuncAttributeMaxDynamicSharedMemorySize, SMEM_BYTES);

    vq_prep<<<64, 256>>>(emb);
    vq_mma_kernel<<<2048, 256, SMEM_BYTES>>>(z, emb, out);
}